// round 12
// baseline (speedup 1.0000x reference)
#include <cuda_runtime.h>
#include <math.h>

#define Nn 50000
#define En 800000
#define Cc 16
#define Mm 32
#define Gg 8
#define CG (Cc*Gg)          // 128

// ---- scratch (module-static, allowed) ----
__device__ float g_smB0[Cc*Mm*Gg];   // softmax(B0, axis=M)   [c][m][g]
__device__ float g_smPi[Cc*Gg];      // softmax(Pi, axis=C)   [c][g]
__device__ float g_smB1[Cc*Mm*Gg];   // softmax(B1, axis=M)   [c][m][g]
__device__ float g_smQ[Cc*Cc*Gg];    // softmax(Q, axis=0)    [i][l][g]
__device__ float g_R[Gg*Mm*Cc];      // R[g][m][i] = sum_l Q[i,l,g]*post0_tab[m][l,g]
__device__ float g_ll0[Mm*Gg];       // ll0_tab[m][g] = log(norm0(m,g))
__device__ int   g_hist[(size_t)Nn*Mm];  // per-node neighbor symbol histogram

// ---------------------------------------------------------------------------
// 1) Softmaxes (threads 0..127) THEN the R / ll0 tables (all 256 threads).
// ---------------------------------------------------------------------------
__global__ void k_softmax(const float* __restrict__ B0, const float* __restrict__ Pi,
                          const float* __restrict__ B1, const float* __restrict__ Q)
{
    int t = threadIdx.x;

    if (t < 128) {
        int g = t & 7;
        int r = t >> 3;

        // B0 row (c=r, g): softmax over m
        {
            float mx = -1e30f;
            #pragma unroll
            for (int m = 0; m < Mm; m++) mx = fmaxf(mx, B0[r*Mm*Gg + m*Gg + g]);
            float e[Mm]; float s = 0.f;
            #pragma unroll
            for (int m = 0; m < Mm; m++) { e[m] = expf(B0[r*Mm*Gg + m*Gg + g] - mx); s += e[m]; }
            float inv = 1.f / s;
            #pragma unroll
            for (int m = 0; m < Mm; m++) g_smB0[r*Mm*Gg + m*Gg + g] = e[m] * inv;
        }
        // B1 row (c=r, g)
        {
            float mx = -1e30f;
            #pragma unroll
            for (int m = 0; m < Mm; m++) mx = fmaxf(mx, B1[r*Mm*Gg + m*Gg + g]);
            float e[Mm]; float s = 0.f;
            #pragma unroll
            for (int m = 0; m < Mm; m++) { e[m] = expf(B1[r*Mm*Gg + m*Gg + g] - mx); s += e[m]; }
            float inv = 1.f / s;
            #pragma unroll
            for (int m = 0; m < Mm; m++) g_smB1[r*Mm*Gg + m*Gg + g] = e[m] * inv;
        }
        // Q column (l=r, g): softmax over i (dim 0)
        {
            float mx = -1e30f;
            #pragma unroll
            for (int i = 0; i < Cc; i++) mx = fmaxf(mx, Q[i*Cc*Gg + r*Gg + g]);
            float e[Cc]; float s = 0.f;
            #pragma unroll
            for (int i = 0; i < Cc; i++) { e[i] = expf(Q[i*Cc*Gg + r*Gg + g] - mx); s += e[i]; }
            float inv = 1.f / s;
            #pragma unroll
            for (int i = 0; i < Cc; i++) g_smQ[i*Cc*Gg + r*Gg + g] = e[i] * inv;
        }
        // Pi column g (threads 0..7): softmax over c
        if (t < Gg) {
            float mx = -1e30f;
            #pragma unroll
            for (int c = 0; c < Cc; c++) mx = fmaxf(mx, Pi[c*Gg + t]);
            float e[Cc]; float s = 0.f;
            #pragma unroll
            for (int c = 0; c < Cc; c++) { e[c] = expf(Pi[c*Gg + t] - mx); s += e[c]; }
            float inv = 1.f / s;
            #pragma unroll
            for (int c = 0; c < Cc; c++) g_smPi[c*Gg + t] = e[c] * inv;
        }
    }
    __syncthreads();

    // Table build: thread t -> (m = t>>3, g = t&7). 256 threads = 32m x 8g.
    {
        int m = t >> 3, g = t & 7;
        float u[Cc]; float s = 0.f;
        #pragma unroll
        for (int l = 0; l < Cc; l++) {
            u[l] = g_smPi[l*Gg + g] * g_smB0[l*Mm*Gg + m*Gg + g];
            s += u[l];
        }
        g_ll0[m*Gg + g] = logf(s);
        float inv = 1.f / s;
        #pragma unroll
        for (int i = 0; i < Cc; i++) {
            float acc = 0.f;
            #pragma unroll
            for (int l = 0; l < Cc; l++)
                acc += g_smQ[i*Cc*Gg + l*Gg + g] * u[l];
            g_R[g*Mm*Cc + m*Cc + i] = acc * inv;
        }
    }
}

// ---------------------------------------------------------------------------
// 2) Zero the histogram (int4, guarded).
// ---------------------------------------------------------------------------
__global__ void k_zero_hist()
{
    int i = blockIdx.x * blockDim.x + threadIdx.x;      // < Nn*32/4 = 400000
    if (i < Nn * Mm / 4)
        reinterpret_cast<int4*>(g_hist)[i] = make_int4(0, 0, 0, 0);
}

// ---------------------------------------------------------------------------
// 3) Histogram scatter: 4 edges per thread.
//    hist[src][x[dst]] += 1  (one 4-byte RED per edge)
// ---------------------------------------------------------------------------
__global__ void k_scatter(const int* __restrict__ ei, const int* __restrict__ x)
{
    int tid = blockIdx.x * blockDim.x + threadIdx.x;
    if (tid >= En / 4) return;
    int e0 = tid * 4;

    const int4 S = *reinterpret_cast<const int4*>(ei + e0);        // 4 src
    const int4 D = *reinterpret_cast<const int4*>(ei + En + e0);   // 4 dst

    int x0 = __ldg(x + D.x);
    int x1 = __ldg(x + D.y);
    int x2 = __ldg(x + D.z);
    int x3 = __ldg(x + D.w);

    atomicAdd(&g_hist[(size_t)S.x * Mm + x0], 1);
    atomicAdd(&g_hist[(size_t)S.y * Mm + x1], 1);
    atomicAdd(&g_hist[(size_t)S.z * Mm + x2], 1);
    atomicAdd(&g_hist[(size_t)S.w * Mm + x3], 1);
}

// ---------------------------------------------------------------------------
// 4) Layer 1 (+ ll0 lookup). Block = 32 nodes x 8 g = 256 threads.
//    tv[i] = sum_m hist[n][m] * R[g][m][i];  cnt = sum_m hist[n][m]
//    v[i]  = B1[i,x[n],g] * tv[i] / max(cnt,1);  norm = sum_i v
//    ll1 = log(norm); post1[i] = v[i]/norm
//    R staged in smem padded to 516 floats/g-row (conflict-free: 516 % 32 = 4),
//    hist rows padded to 33 ints (conflict-free broadcast).
// ---------------------------------------------------------------------------
__global__ void k_layer1(const int* __restrict__ x, float* __restrict__ out)
{
    __shared__ float s_R[Gg * 516];      // 16.5 KB
    __shared__ int   s_hist[32 * 33];    // 4.2 KB
    __shared__ int   s_x[32];

    int t   = threadIdx.x;
    int bn0 = blockIdx.x * 32;

    // cooperative load of R: thread t -> 16 consecutive floats of g-row (t>>5)
    {
        int g   = t >> 5;
        int rem = (t & 31) * 16;
        const float4* src = reinterpret_cast<const float4*>(g_R + g * (Mm*Cc) + rem);
        float4*       dst = reinterpret_cast<float4*>(s_R + g * 516 + rem);
        dst[0] = src[0]; dst[1] = src[1]; dst[2] = src[2]; dst[3] = src[3];
    }
    // cooperative load of hist: thread t -> 4 ints of node-row (t>>3)
    {
        int nl  = t >> 3;
        int col = (t & 7) * 4;
        if (bn0 + nl < Nn) {
            int4 h4 = *reinterpret_cast<const int4*>(g_hist + (size_t)(bn0 + nl) * Mm + col);
            int* hp = s_hist + nl * 33 + col;
            hp[0] = h4.x; hp[1] = h4.y; hp[2] = h4.z; hp[3] = h4.w;
        }
    }
    if (t < 32 && bn0 + t < Nn) s_x[t] = x[bn0 + t];
    __syncthreads();

    int nl = t >> 3, g = t & 7;
    int n  = bn0 + nl;
    if (n >= Nn) return;
    int xm = s_x[nl];

    float tv[Cc];
    #pragma unroll
    for (int i = 0; i < Cc; i++) tv[i] = 0.f;
    float cnt = 0.f;

    const float* Rg = s_R + g * 516;
    const int*   hp = s_hist + nl * 33;

    #pragma unroll
    for (int m = 0; m < Mm; m++) {
        float h = (float)hp[m];
        cnt += h;
        const float4* r4 = reinterpret_cast<const float4*>(Rg + m * Cc);
        float4 r0 = r4[0], r1 = r4[1], r2 = r4[2], r3 = r4[3];
        tv[ 0] += h * r0.x; tv[ 1] += h * r0.y; tv[ 2] += h * r0.z; tv[ 3] += h * r0.w;
        tv[ 4] += h * r1.x; tv[ 5] += h * r1.y; tv[ 6] += h * r1.z; tv[ 7] += h * r1.w;
        tv[ 8] += h * r2.x; tv[ 9] += h * r2.y; tv[10] += h * r2.z; tv[11] += h * r2.w;
        tv[12] += h * r3.x; tv[13] += h * r3.y; tv[14] += h * r3.z; tv[15] += h * r3.w;
    }

    float inv_cnt = 1.f / fmaxf(cnt, 1.f);
    float norm = 0.f;
    #pragma unroll
    for (int i = 0; i < Cc; i++) {
        float v = g_smB1[i*Mm*Gg + xm*Gg + g] * tv[i] * inv_cnt;
        tv[i] = v;
        norm += v;
    }

    out[(size_t)n * (2*Gg) + g]      = g_ll0[xm*Gg + g];   // ll layer 0
    out[(size_t)n * (2*Gg) + Gg + g] = logf(norm);         // ll layer 1

    float invn = 1.f / norm;
    float* p1 = out + (size_t)Nn * 2 * Gg;
    size_t pbase = (size_t)n * CG + g;
    #pragma unroll
    for (int i = 0; i < Cc; i++) p1[pbase + i*Gg] = tv[i] * invn;
}

// ---------------------------------------------------------------------------
extern "C" void kernel_launch(void* const* d_in, const int* in_sizes, int n_in,
                              void* d_out, int out_size)
{
    const int*   x  = (const int*)  d_in[0];
    const int*   ei = (const int*)  d_in[1];   // [2, E]
    const float* B0 = (const float*)d_in[2];
    const float* Pi = (const float*)d_in[3];
    const float* B1 = (const float*)d_in[4];
    const float* Q  = (const float*)d_in[5];
    float* out = (float*)d_out;

    k_softmax<<<1, 256>>>(B0, Pi, B1, Q);
    k_zero_hist<<<(Nn * Mm / 4 + 255) / 256, 256>>>();
    k_scatter<<<(En / 4 + 255) / 256, 256>>>(ei, x);
    k_layer1<<<(Nn + 31) / 32, 256>>>(x, out);
}

// round 13
// speedup vs baseline: 1.3954x; 1.3954x over previous
#include <cuda_runtime.h>
#include <math.h>

#define Nn 50000
#define En 800000
#define Cc 16
#define Mm 32
#define Gg 8
#define CG (Cc*Gg)          // 128
#define NODES_PB 128        // nodes per layer1 block

// ---- scratch (module-static, allowed) ----
__device__ float g_smB0[Cc*Mm*Gg];   // softmax(B0, axis=M)   [c][m][g]
__device__ float g_smPi[Cc*Gg];      // softmax(Pi, axis=C)   [c][g]
__device__ float g_smB1[Cc*Mm*Gg];   // softmax(B1, axis=M)   [c][m][g]
__device__ float g_smQ[Cc*Cc*Gg];    // softmax(Q, axis=0)    [i][l][g]
__device__ float g_R[Gg*Mm*Cc];      // R[g][m][i] = sum_l Q[i,l,g]*post0_tab[m][l,g]
__device__ float g_ll0[Mm*Gg];       // ll0_tab[m][g] = log(norm0(m,g))
__device__ int   g_hist[(size_t)Nn*Mm];  // per-node neighbor symbol histogram

// ---------------------------------------------------------------------------
// 1) Fused init. Block 0: softmaxes + R/ll0 tables. Blocks >= 1: zero hist.
// ---------------------------------------------------------------------------
__global__ void k_init(const float* __restrict__ B0, const float* __restrict__ Pi,
                       const float* __restrict__ B1, const float* __restrict__ Q)
{
    if (blockIdx.x > 0) {
        int i = (blockIdx.x - 1) * blockDim.x + threadIdx.x;
        if (i < Nn * Mm / 4)
            reinterpret_cast<int4*>(g_hist)[i] = make_int4(0, 0, 0, 0);
        return;
    }

    int t = threadIdx.x;
    if (t < 128) {
        int g = t & 7;
        int r = t >> 3;
        // B0 row (c=r, g): softmax over m
        {
            float mx = -1e30f;
            #pragma unroll
            for (int m = 0; m < Mm; m++) mx = fmaxf(mx, B0[r*Mm*Gg + m*Gg + g]);
            float e[Mm]; float s = 0.f;
            #pragma unroll
            for (int m = 0; m < Mm; m++) { e[m] = expf(B0[r*Mm*Gg + m*Gg + g] - mx); s += e[m]; }
            float inv = 1.f / s;
            #pragma unroll
            for (int m = 0; m < Mm; m++) g_smB0[r*Mm*Gg + m*Gg + g] = e[m] * inv;
        }
        // B1 row (c=r, g)
        {
            float mx = -1e30f;
            #pragma unroll
            for (int m = 0; m < Mm; m++) mx = fmaxf(mx, B1[r*Mm*Gg + m*Gg + g]);
            float e[Mm]; float s = 0.f;
            #pragma unroll
            for (int m = 0; m < Mm; m++) { e[m] = expf(B1[r*Mm*Gg + m*Gg + g] - mx); s += e[m]; }
            float inv = 1.f / s;
            #pragma unroll
            for (int m = 0; m < Mm; m++) g_smB1[r*Mm*Gg + m*Gg + g] = e[m] * inv;
        }
        // Q column (l=r, g): softmax over i (dim 0)
        {
            float mx = -1e30f;
            #pragma unroll
            for (int i = 0; i < Cc; i++) mx = fmaxf(mx, Q[i*Cc*Gg + r*Gg + g]);
            float e[Cc]; float s = 0.f;
            #pragma unroll
            for (int i = 0; i < Cc; i++) { e[i] = expf(Q[i*Cc*Gg + r*Gg + g] - mx); s += e[i]; }
            float inv = 1.f / s;
            #pragma unroll
            for (int i = 0; i < Cc; i++) g_smQ[i*Cc*Gg + r*Gg + g] = e[i] * inv;
        }
        // Pi column g (threads 0..7): softmax over c
        if (t < Gg) {
            float mx = -1e30f;
            #pragma unroll
            for (int c = 0; c < Cc; c++) mx = fmaxf(mx, Pi[c*Gg + t]);
            float e[Cc]; float s = 0.f;
            #pragma unroll
            for (int c = 0; c < Cc; c++) { e[c] = expf(Pi[c*Gg + t] - mx); s += e[c]; }
            float inv = 1.f / s;
            #pragma unroll
            for (int c = 0; c < Cc; c++) g_smPi[c*Gg + t] = e[c] * inv;
        }
    }
    __syncthreads();

    // Table build: thread t -> (m = t>>3, g = t&7). 256 threads = 32m x 8g.
    {
        int m = t >> 3, g = t & 7;
        float u[Cc]; float s = 0.f;
        #pragma unroll
        for (int l = 0; l < Cc; l++) {
            u[l] = g_smPi[l*Gg + g] * g_smB0[l*Mm*Gg + m*Gg + g];
            s += u[l];
        }
        g_ll0[m*Gg + g] = logf(s);
        float inv = 1.f / s;
        #pragma unroll
        for (int i = 0; i < Cc; i++) {
            float acc = 0.f;
            #pragma unroll
            for (int l = 0; l < Cc; l++)
                acc += g_smQ[i*Cc*Gg + l*Gg + g] * u[l];
            g_R[g*Mm*Cc + m*Cc + i] = acc * inv;
        }
    }
}

// ---------------------------------------------------------------------------
// 2) Histogram scatter: 4 edges per thread.  hist[src][x[dst]] += 1
// ---------------------------------------------------------------------------
__global__ void k_scatter(const int* __restrict__ ei, const int* __restrict__ x)
{
    int tid = blockIdx.x * blockDim.x + threadIdx.x;
    if (tid >= En / 4) return;
    int e0 = tid * 4;

    const int4 S = *reinterpret_cast<const int4*>(ei + e0);        // 4 src
    const int4 D = *reinterpret_cast<const int4*>(ei + En + e0);   // 4 dst

    int x0 = __ldg(x + D.x);
    int x1 = __ldg(x + D.y);
    int x2 = __ldg(x + D.z);
    int x3 = __ldg(x + D.w);

    atomicAdd(&g_hist[(size_t)S.x * Mm + x0], 1);
    atomicAdd(&g_hist[(size_t)S.y * Mm + x1], 1);
    atomicAdd(&g_hist[(size_t)S.z * Mm + x2], 1);
    atomicAdd(&g_hist[(size_t)S.w * Mm + x3], 1);
}

// ---------------------------------------------------------------------------
// 3) Layer 1 (+ ll0 lookup). Block = 256 threads covering 128 nodes.
//    Thread (q = t>>3, g = t&7) processes FOUR nodes (q*4..q*4+3) so each
//    R[g][m][:] tile load (4x LDS.128) feeds 64 FMAs instead of 16.
//    hist staged in smem as FLOATS (converts once at load, not in the loop).
//    s_R rows padded to 516 (conflict-free), s_h rows padded to 33.
// ---------------------------------------------------------------------------
__global__ void k_layer1(const int* __restrict__ x, float* __restrict__ out)
{
    __shared__ float s_R[Gg * 516];          // 16.5 KB
    __shared__ float s_h[NODES_PB * 33];     // 16.9 KB
    __shared__ int   s_x[NODES_PB];

    int t   = threadIdx.x;
    int bn0 = blockIdx.x * NODES_PB;

    // cooperative load of R: thread t -> 16 consecutive floats of g-row (t>>5)
    {
        int g   = t >> 5;
        int rem = (t & 31) * 16;
        const float4* src = reinterpret_cast<const float4*>(g_R + g * (Mm*Cc) + rem);
        float4*       dst = reinterpret_cast<float4*>(s_R + g * 516 + rem);
        dst[0] = src[0]; dst[1] = src[1]; dst[2] = src[2]; dst[3] = src[3];
    }
    // cooperative load of hist (int -> float): thread t -> half a row (16 vals)
    {
        int row = t >> 1;
        int cb  = (t & 1) * 16;
        if (bn0 + row < Nn) {
            const int4* src = reinterpret_cast<const int4*>(
                g_hist + (size_t)(bn0 + row) * Mm + cb);
            float* dp = s_h + row * 33 + cb;
            #pragma unroll
            for (int q = 0; q < 4; q++) {
                int4 v = src[q];
                dp[q*4+0] = (float)v.x; dp[q*4+1] = (float)v.y;
                dp[q*4+2] = (float)v.z; dp[q*4+3] = (float)v.w;
            }
        }
    }
    if (t < NODES_PB && bn0 + t < Nn) s_x[t] = x[bn0 + t];
    __syncthreads();

    int q = t >> 3, g = t & 7;          // q: 0..31 -> nodes q*4 .. q*4+3
    int nb = q * 4;

    float tv[4][Cc];
    #pragma unroll
    for (int j = 0; j < 4; j++)
        #pragma unroll
        for (int i = 0; i < Cc; i++) tv[j][i] = 0.f;
    float cnt[4] = {0.f, 0.f, 0.f, 0.f};

    const float* Rg = s_R + g * 516;
    const float* h0 = s_h + (nb + 0) * 33;
    const float* h1 = s_h + (nb + 1) * 33;
    const float* h2 = s_h + (nb + 2) * 33;
    const float* h3 = s_h + (nb + 3) * 33;

    #pragma unroll 4
    for (int m = 0; m < Mm; m++) {
        const float4* r4 = reinterpret_cast<const float4*>(Rg + m * Cc);
        float4 r0 = r4[0], r1 = r4[1], r2 = r4[2], r3 = r4[3];
        float a0 = h0[m], a1 = h1[m], a2 = h2[m], a3 = h3[m];
        cnt[0] += a0; cnt[1] += a1; cnt[2] += a2; cnt[3] += a3;

        tv[0][ 0] += a0*r0.x; tv[0][ 1] += a0*r0.y; tv[0][ 2] += a0*r0.z; tv[0][ 3] += a0*r0.w;
        tv[0][ 4] += a0*r1.x; tv[0][ 5] += a0*r1.y; tv[0][ 6] += a0*r1.z; tv[0][ 7] += a0*r1.w;
        tv[0][ 8] += a0*r2.x; tv[0][ 9] += a0*r2.y; tv[0][10] += a0*r2.z; tv[0][11] += a0*r2.w;
        tv[0][12] += a0*r3.x; tv[0][13] += a0*r3.y; tv[0][14] += a0*r3.z; tv[0][15] += a0*r3.w;

        tv[1][ 0] += a1*r0.x; tv[1][ 1] += a1*r0.y; tv[1][ 2] += a1*r0.z; tv[1][ 3] += a1*r0.w;
        tv[1][ 4] += a1*r1.x; tv[1][ 5] += a1*r1.y; tv[1][ 6] += a1*r1.z; tv[1][ 7] += a1*r1.w;
        tv[1][ 8] += a1*r2.x; tv[1][ 9] += a1*r2.y; tv[1][10] += a1*r2.z; tv[1][11] += a1*r2.w;
        tv[1][12] += a1*r3.x; tv[1][13] += a1*r3.y; tv[1][14] += a1*r3.z; tv[1][15] += a1*r3.w;

        tv[2][ 0] += a2*r0.x; tv[2][ 1] += a2*r0.y; tv[2][ 2] += a2*r0.z; tv[2][ 3] += a2*r0.w;
        tv[2][ 4] += a2*r1.x; tv[2][ 5] += a2*r1.y; tv[2][ 6] += a2*r1.z; tv[2][ 7] += a2*r1.w;
        tv[2][ 8] += a2*r2.x; tv[2][ 9] += a2*r2.y; tv[2][10] += a2*r2.z; tv[2][11] += a2*r2.w;
        tv[2][12] += a2*r3.x; tv[2][13] += a2*r3.y; tv[2][14] += a2*r3.z; tv[2][15] += a2*r3.w;

        tv[3][ 0] += a3*r0.x; tv[3][ 1] += a3*r0.y; tv[3][ 2] += a3*r0.z; tv[3][ 3] += a3*r0.w;
        tv[3][ 4] += a3*r1.x; tv[3][ 5] += a3*r1.y; tv[3][ 6] += a3*r1.z; tv[3][ 7] += a3*r1.w;
        tv[3][ 8] += a3*r2.x; tv[3][ 9] += a3*r2.y; tv[3][10] += a3*r2.z; tv[3][11] += a3*r2.w;
        tv[3][12] += a3*r3.x; tv[3][13] += a3*r3.y; tv[3][14] += a3*r3.z; tv[3][15] += a3*r3.w;
    }

    float* p1 = out + (size_t)Nn * 2 * Gg;

    #pragma unroll
    for (int j = 0; j < 4; j++) {
        int n = bn0 + nb + j;
        if (n >= Nn) break;
        int xm = s_x[nb + j];
        float inv_cnt = 1.f / fmaxf(cnt[j], 1.f);
        float v[Cc]; float norm = 0.f;
        #pragma unroll
        for (int i = 0; i < Cc; i++) {
            float w = g_smB1[i*Mm*Gg + xm*Gg + g] * tv[j][i] * inv_cnt;
            v[i] = w;
            norm += w;
        }
        out[(size_t)n * (2*Gg) + g]      = g_ll0[xm*Gg + g];
        out[(size_t)n * (2*Gg) + Gg + g] = logf(norm);
        float invn = 1.f / norm;
        size_t pbase = (size_t)n * CG + g;
        #pragma unroll
        for (int i = 0; i < Cc; i++) p1[pbase + i*Gg] = v[i] * invn;
    }
}

// ---------------------------------------------------------------------------
extern "C" void kernel_launch(void* const* d_in, const int* in_sizes, int n_in,
                              void* d_out, int out_size)
{
    const int*   x  = (const int*)  d_in[0];
    const int*   ei = (const int*)  d_in[1];   // [2, E]
    const float* B0 = (const float*)d_in[2];
    const float* Pi = (const float*)d_in[3];
    const float* B1 = (const float*)d_in[4];
    const float* Q  = (const float*)d_in[5];
    float* out = (float*)d_out;

    // block 0: softmax+tables; blocks 1..1563: zero hist
    k_init<<<1 + (Nn * Mm / 4 + 255) / 256, 256>>>(B0, Pi, B1, Q);
    k_scatter<<<(En / 4 + 255) / 256, 256>>>(ei, x);
    k_layer1<<<(Nn + NODES_PB - 1) / NODES_PB, 256>>>(x, out);
}